// round 1
// baseline (speedup 1.0000x reference)
#include <cuda_runtime.h>

// Problem shape (fixed by dataset): x_hr (16,3,512,512) f32, w1 (3,9) f32.
#define BB 16
#define CH 3
#define HH 512
#define WW 512
#define HW (HH*WW)
#define NPIX (BB*HW)

// Scratch: single-channel per-pixel maps (allowed as __device__ globals).
__device__ float g_u[NPIX];   // sum_c x
__device__ float g_v[NPIX];   // sum_c x^2
__device__ float g_A1[NPIX];  // cumulative affine after stage 1: F1 = A1*x + C1
__device__ float g_C1[NPIX];
__device__ float g_A2[NPIX];  // cumulative affine after stage 2: F2 = A2*x + C2
__device__ float g_C2[NPIX];

__global__ void __launch_bounds__(256) uv_kernel(const float* __restrict__ x) {
    int p = blockIdx.x * 256 + threadIdx.x;
    if (p >= NPIX) return;
    int b = p >> 18;            // / HW (HW = 262144 = 2^18)
    int q = p & (HW - 1);
    const float* xb = x + (size_t)b * 3 * HW + q;
    float x0 = xb[0], x1 = xb[HW], x2 = xb[2 * HW];
    g_u[p] = x0 + x1 + x2;
    g_v[p] = x0 * x0 + x1 * x1 + x2 * x2;
}

// One guided-filter stage, fully fused:
//   s1,s2 (channel sums of stage input, derived pointwise from u,v + cum affine)
//   -> box_k -> (m,q,var,A,b) -> box_k -> (a = 3*sumA, c = 3*sumB)
//   -> update cumulative affine (stages 1,2) or final 1x1-conv output (stage 3).
// Box filters are separable sliding-window passes in shared memory.
template <int R, int STAGE>
__global__ void __launch_bounds__(256) stage_kernel(const float* __restrict__ x,
                                                    const float* __restrict__ wg,
                                                    float* __restrict__ out) {
    constexpr int T  = 64;
    constexpr int K  = 2 * R + 1;
    constexpr int E1 = T + 2 * R;   // region where A,b are needed
    constexpr int E2 = T + 4 * R;   // region where s is needed
    constexpr int SP = E2 + 1;      // odd row stride -> conflict-free
    constexpr int HP = E1 + 1;      // odd row stride
    constexpr float EPS = (STAGE == 1) ? 0.16f : ((STAGE == 2) ? 0.04f : 0.01f);

    extern __shared__ float sm[];
    float* S1 = sm;                 // s1 tile, later A tile, later raw sumA
    float* S2 = S1 + E2 * SP;       // s2 tile, later b tile, later raw sumB
    float* H1 = S2 + E2 * SP;       // horizontal box scratch (map 1)
    float* H2 = H1 + E2 * HP;       // horizontal box scratch (map 2)

    const int tid = threadIdx.x;
    const int gx0 = blockIdx.x * T;
    const int gy0 = blockIdx.y * T;
    const int b   = blockIdx.z;
    const int gb  = b * HW;

    __shared__ float sw[27];
    if (STAGE == 3 && tid < 27) sw[tid] = wg[tid];

    // ---- load s1,s2 over E2 x E2 (zero padding outside the image) ----
    for (int idx = tid; idx < E2 * E2; idx += 256) {
        int iy = idx / E2, ix = idx - iy * E2;
        int gy = gy0 - 2 * R + iy, gx = gx0 - 2 * R + ix;
        float s1 = 0.f, s2 = 0.f;
        if ((unsigned)gy < (unsigned)HH && (unsigned)gx < (unsigned)WW) {
            int g = gb + gy * WW + gx;
            float u = g_u[g], v = g_v[g];
            if (STAGE == 1) {
                s1 = u; s2 = v;
            } else {
                float Ac = (STAGE == 2) ? g_A1[g] : g_A2[g];
                float Cc = (STAGE == 2) ? g_C1[g] : g_C2[g];
                // F_c = Ac*x_c + Cc  =>  sum_c F = Ac*u + 3Cc ; sum_c F^2 = Ac^2 v + 2AcCc u + 3Cc^2
                s1 = fmaf(Ac, u, 3.f * Cc);
                s2 = fmaf(Ac * Ac, v, fmaf(2.f * Ac * Cc, u, 3.f * Cc * Cc));
            }
        }
        S1[iy * SP + ix] = s1;
        S2[iy * SP + ix] = s2;
    }
    __syncthreads();

    // ---- box #1, horizontal: H[r][c] = sum_{j=c..c+2R} S[r][j], r<E2, c<E1 ----
    for (int t = tid; t < 2 * E2; t += 256) {
        const float* src = (t < E2) ? S1 : S2;
        float* dst = (t < E2) ? H1 : H2;
        int r = (t < E2) ? t : t - E2;
        const float* row = src + r * SP;
        float* orow = dst + r * HP;
        float s = 0.f;
#pragma unroll
        for (int j = 0; j < K; ++j) s += row[j];
        orow[0] = s;
        for (int c = 1; c < E1; ++c) { s += row[c + 2 * R] - row[c - 1]; orow[c] = s; }
    }
    __syncthreads();

    // ---- box #1 vertical + pointwise -> A,b over E1 x E1 (into S1,S2) ----
    for (int c = tid; c < E1; c += 256) {
        float r1 = 0.f, r2 = 0.f;
#pragma unroll
        for (int j = 0; j < K; ++j) { r1 += H1[j * HP + c]; r2 += H2[j * HP + c]; }
        const int gx = gx0 - R + c;
        for (int i = 0; i < E1; ++i) {
            int gy = gy0 - R + i;
            float A = 0.f, bv = 0.f;
            if ((unsigned)gy < (unsigned)HH && (unsigned)gx < (unsigned)WW) {
                int cy = min(gy + R, HH - 1) - max(gy - R, 0) + 1;
                int cx = min(gx + R, WW - 1) - max(gx - R, 0) + 1;
                float inv = __frcp_rn(3.f * (float)(cy * cx));   // 1/Nc
                float m = r1 * inv, q = r2 * inv;
                float var = fmaf(-m, m, q);
                A = __fdividef(var, var + EPS);
                bv = m - A * m;
            }
            S1[i * SP + c] = A;
            S2[i * SP + c] = bv;
            if (i + 1 < E1) {
                r1 += H1[(i + K) * HP + c] - H1[i * HP + c];
                r2 += H2[(i + K) * HP + c] - H2[i * HP + c];
            }
        }
    }
    __syncthreads();

    // ---- box #2, horizontal: H[r][c] = sum_{j=c..c+2R} Ab[r][j], r<E1, c<T ----
    for (int t = tid; t < 2 * E1; t += 256) {
        const float* src = (t < E1) ? S1 : S2;
        float* dst = (t < E1) ? H1 : H2;
        int r = (t < E1) ? t : t - E1;
        const float* row = src + r * SP;
        float* orow = dst + r * HP;
        float s = 0.f;
#pragma unroll
        for (int j = 0; j < K; ++j) s += row[j];
        orow[0] = s;
        for (int c = 1; c < T; ++c) { s += row[c + 2 * R] - row[c - 1]; orow[c] = s; }
    }
    __syncthreads();

    // ---- box #2 vertical -> raw sums over T x T (into S1,S2) ----
    for (int c = tid; c < T; c += 256) {
        float r1 = 0.f, r2 = 0.f;
#pragma unroll
        for (int j = 0; j < K; ++j) { r1 += H1[j * HP + c]; r2 += H2[j * HP + c]; }
        for (int i = 0; i < T; ++i) {
            S1[i * SP + c] = r1;
            S2[i * SP + c] = r2;
            if (i + 1 < T) {
                r1 += H1[(i + K) * HP + c] - H1[i * HP + c];
                r2 += H2[(i + K) * HP + c] - H2[i * HP + c];
            }
        }
    }
    __syncthreads();

    // ---- epilogue: cumulative affine update / final 1x1 conv ----
    for (int idx = tid; idx < T * T; idx += 256) {
        int i = idx / T, c = idx - i * T;
        int gy = gy0 + i, gx = gx0 + c;
        int g = gb + gy * WW + gx;
        float a  = 3.f * S1[i * SP + c];   // mean_A = C * box(A), C=3
        float cc = 3.f * S2[i * SP + c];   // mean_b = C * box(b)
        if (STAGE == 1) {
            g_A1[g] = a;
            g_C1[g] = cc;
        } else if (STAGE == 2) {
            float A1 = g_A1[g], C1 = g_C1[g];
            g_A2[g] = a * A1;
            g_C2[g] = fmaf(a, C1, cc);
        } else {
            float A1 = g_A1[g], C1 = g_C1[g];
            float A2 = g_A2[g], C2 = g_C2[g];
            float A3 = a * A2, C3 = fmaf(a, C2, cc);
            // D_{3j+c} = al[j]*x_c + be[j]
            float al0 = 1.f - A1, be0 = -C1;
            float al1 = A1 - A2,  be1 = C1 - C2;
            float al2 = A2 - A3,  be2 = C2 - C3;
            const float* xp = x + (size_t)b * 3 * HW + gy * WW + gx;
            float x0 = xp[0], x1 = xp[HW], x2 = xp[2 * HW];
            float al[3] = {al0, al1, al2};
            float be[3] = {be0, be1, be2};
#pragma unroll
            for (int o = 0; o < 3; ++o) {
                float acc = 0.f;
#pragma unroll
                for (int j = 0; j < 3; ++j) {
                    float w0 = sw[o * 9 + j * 3 + 0];
                    float w1 = sw[o * 9 + j * 3 + 1];
                    float w2 = sw[o * 9 + j * 3 + 2];
                    acc += al[j] * (w0 * x0 + w1 * x1 + w2 * x2)
                         + be[j] * (w0 + w1 + w2);
                }
                out[(size_t)(b * 3 + o) * HW + (size_t)gy * WW + gx] = acc;
            }
        }
    }
}

// smem bytes per stage
static constexpr int smem_bytes(int R) {
    int T = 64, E1 = T + 2 * R, E2 = T + 4 * R;
    return (2 * E2 * (E2 + 1) + 2 * E2 * (E1 + 1)) * 4;
}

extern "C" void kernel_launch(void* const* d_in, const int* in_sizes, int n_in,
                              void* d_out, int out_size) {
    const float* x  = (const float*)d_in[0];
    const float* wg = (const float*)d_in[1];
    float* out = (float*)d_out;

    constexpr int S1B = smem_bytes(1);   // ~74 KB
    constexpr int S2B = smem_bytes(3);   // ~90 KB
    constexpr int S3B = smem_bytes(7);   // ~127 KB
    cudaFuncSetAttribute(stage_kernel<1, 1>, cudaFuncAttributeMaxDynamicSharedMemorySize, S1B);
    cudaFuncSetAttribute(stage_kernel<3, 2>, cudaFuncAttributeMaxDynamicSharedMemorySize, S2B);
    cudaFuncSetAttribute(stage_kernel<7, 3>, cudaFuncAttributeMaxDynamicSharedMemorySize, S3B);

    uv_kernel<<<NPIX / 256, 256>>>(x);

    dim3 grid(WW / 64, HH / 64, BB);
    stage_kernel<1, 1><<<grid, 256, S1B>>>(x, wg, out);
    stage_kernel<3, 2><<<grid, 256, S2B>>>(x, wg, out);
    stage_kernel<7, 3><<<grid, 256, S3B>>>(x, wg, out);
}

// round 2
// speedup vs baseline: 1.9135x; 1.9135x over previous
#include <cuda_runtime.h>

// Problem shape (fixed by dataset): x_hr (16,3,512,512) f32, w1 (3,9) f32.
#define BB 16
#define HH 512
#define WW 512
#define HW (HH*WW)
#define NPIX (BB*HW)
#define NT 512   // threads per block

// Scratch: single-channel per-pixel maps (__device__ globals are allowed).
__device__ float g_u[NPIX];   // sum_c x
__device__ float g_v[NPIX];   // sum_c x^2
__device__ float g_A1[NPIX];  // cumulative affine after stage 1: F1 = A1*x + C1
__device__ float g_C1[NPIX];
__device__ float g_A2[NPIX];  // cumulative affine after stage 2: F2 = A2*x + C2
__device__ float g_C2[NPIX];

// One guided-filter stage, fully fused (box -> pointwise -> box -> epilogue),
// all passes segmented so every phase keeps ~NT lanes busy.
template <int R, int STAGE>
__global__ void __launch_bounds__(NT) stage_kernel(const float* __restrict__ x,
                                                   const float* __restrict__ wg,
                                                   float* __restrict__ out) {
    constexpr int T  = 64;
    constexpr int K  = 2 * R + 1;
    constexpr int E1 = T + 2 * R;   // region where A,b are needed
    constexpr int E2 = T + 4 * R;   // region where channel sums are needed
    constexpr int SP = E2 + 1;      // odd strides -> conflict-free
    constexpr int HP = E1 + 1;
    constexpr float EPS = (STAGE == 1) ? 0.16f : ((STAGE == 2) ? 0.04f : 0.01f);

    // segment counts per pass (keep ~NT work items)
    constexpr int NS1 = (NT + 2 * E2 - 1) / (2 * E2);  // horiz pass 1
    constexpr int LS1 = (E1 + NS1 - 1) / NS1;
    constexpr int NV1 = (NT + E1 - 1) / E1;            // vert pass 1
    constexpr int LV1 = (E1 + NV1 - 1) / NV1;
    constexpr int NS2 = (NT + 2 * E1 - 1) / (2 * E1);  // horiz pass 2
    constexpr int LS2 = (T + NS2 - 1) / NS2;
    constexpr int NV2 = NT / T;                        // vert pass 2 (=8)
    constexpr int LV2 = (T + NV2 - 1) / NV2;

    extern __shared__ float sm[];
    float* S1 = sm;                 // s1 tile, later A tile
    float* S2 = S1 + E2 * SP;       // s2 tile, later b tile
    float* H1 = S2 + E2 * SP;       // horizontal box scratch
    float* H2 = H1 + E2 * HP;

    const int tid = threadIdx.x;
    const int gx0 = blockIdx.x * T;
    const int gy0 = blockIdx.y * T;
    const int b   = blockIdx.z;
    const int gb  = b * HW;

    __shared__ float sw[27];
    if (STAGE == 3 && tid < 27) sw[tid] = wg[tid];

    // ---- load channel-sum maps over E2 x E2 (zero padding outside image) ----
    for (int idx = tid; idx < E2 * E2; idx += NT) {
        int iy = idx / E2, ix = idx - iy * E2;
        int gy = gy0 - 2 * R + iy, gx = gx0 - 2 * R + ix;
        float s1 = 0.f, s2 = 0.f;
        if ((unsigned)gy < (unsigned)HH && (unsigned)gx < (unsigned)WW) {
            int g = gb + gy * WW + gx;
            if (STAGE == 1) {
                const float* xb = x + (size_t)b * 3 * HW + gy * WW + gx;
                float x0 = xb[0], x1 = xb[HW], x2 = xb[2 * HW];
                s1 = x0 + x1 + x2;
                s2 = x0 * x0 + x1 * x1 + x2 * x2;
                // persist u,v for later stages (interior pixels only)
                if (iy >= 2 * R && iy < 2 * R + T && ix >= 2 * R && ix < 2 * R + T) {
                    g_u[g] = s1; g_v[g] = s2;
                }
            } else {
                float u = g_u[g], v = g_v[g];
                float Ac = (STAGE == 2) ? g_A1[g] : g_A2[g];
                float Cc = (STAGE == 2) ? g_C1[g] : g_C2[g];
                // F_c = Ac*x_c + Cc : sum_c F = Ac*u + 3Cc ; sum_c F^2 = Ac^2 v + 2AcCc u + 3Cc^2
                s1 = fmaf(Ac, u, 3.f * Cc);
                s2 = fmaf(Ac * Ac, v, fmaf(2.f * Ac * Cc, u, 3.f * Cc * Cc));
            }
        }
        S1[iy * SP + ix] = s1;
        S2[iy * SP + ix] = s2;
    }
    __syncthreads();

    // ---- box #1 horizontal: H[r][c] = sum_{j=c..c+2R} S[r][j], r<E2, c<E1 ----
    for (int item = tid; item < 2 * E2 * NS1; item += NT) {
        int r = item % E2;
        int rest = item / E2;
        int m = rest & 1, seg = rest >> 1;
        int c0 = seg * LS1, c1 = min(E1, c0 + LS1);
        if (c0 >= c1) continue;
        const float* row = (m ? S2 : S1) + r * SP;
        float* orow = (m ? H2 : H1) + r * HP;
        float s = 0.f;
#pragma unroll
        for (int j = 0; j < K; ++j) s += row[c0 + j];
        orow[c0] = s;
        for (int c = c0 + 1; c < c1; ++c) { s += row[c + 2 * R] - row[c - 1]; orow[c] = s; }
    }
    __syncthreads();

    // ---- box #1 vertical + pointwise -> A,b over E1 x E1 (into S1,S2) ----
    for (int item = tid; item < E1 * NV1; item += NT) {
        int c = item % E1;
        int seg = item / E1;
        int r0 = seg * LV1, r1e = min(E1, r0 + LV1);
        if (r0 >= r1e) continue;
        float r1 = 0.f, r2 = 0.f;
#pragma unroll
        for (int j = 0; j < K; ++j) { r1 += H1[(r0 + j) * HP + c]; r2 += H2[(r0 + j) * HP + c]; }
        const int gx = gx0 - R + c;
        for (int i = r0; i < r1e; ++i) {
            int gy = gy0 - R + i;
            float A = 0.f, bv = 0.f;
            if ((unsigned)gy < (unsigned)HH && (unsigned)gx < (unsigned)WW) {
                int cy = min(gy + R, HH - 1) - max(gy - R, 0) + 1;
                int cx = min(gx + R, WW - 1) - max(gx - R, 0) + 1;
                float inv = __frcp_rn(3.f * (float)(cy * cx));   // 1/Nc
                float m = r1 * inv, q = r2 * inv;
                float var = fmaf(-m, m, q);
                A = __fdividef(var, var + EPS);
                bv = m - A * m;
            }
            S1[i * SP + c] = A;
            S2[i * SP + c] = bv;
            if (i + 1 < r1e) {
                r1 += H1[(i + K) * HP + c] - H1[i * HP + c];
                r2 += H2[(i + K) * HP + c] - H2[i * HP + c];
            }
        }
    }
    __syncthreads();

    // ---- box #2 horizontal: H[r][c] = sum_{j=c..c+2R} Ab[r][j], r<E1, c<T ----
    for (int item = tid; item < 2 * E1 * NS2; item += NT) {
        int r = item % E1;
        int rest = item / E1;
        int m = rest & 1, seg = rest >> 1;
        int c0 = seg * LS2, c1 = min(T, c0 + LS2);
        if (c0 >= c1) continue;
        const float* row = (m ? S2 : S1) + r * SP;
        float* orow = (m ? H2 : H1) + r * HP;
        float s = 0.f;
#pragma unroll
        for (int j = 0; j < K; ++j) s += row[c0 + j];
        orow[c0] = s;
        for (int c = c0 + 1; c < c1; ++c) { s += row[c + 2 * R] - row[c - 1]; orow[c] = s; }
    }
    __syncthreads();

    // ---- box #2 vertical + fused epilogue over T x T ----
    for (int item = tid; item < T * NV2; item += NT) {
        int c = item % T;
        int seg = item / T;
        int r0 = seg * LV2, r1e = min(T, r0 + LV2);
        if (r0 >= r1e) continue;
        float r1 = 0.f, r2 = 0.f;
#pragma unroll
        for (int j = 0; j < K; ++j) { r1 += H1[(r0 + j) * HP + c]; r2 += H2[(r0 + j) * HP + c]; }
        int gx = gx0 + c;
        for (int i = r0; i < r1e; ++i) {
            int gy = gy0 + i;
            int g = gb + gy * WW + gx;
            float a  = 3.f * r1;   // mean_A = C * box(A), C = 3
            float cc = 3.f * r2;   // mean_b = C * box(b)
            if (STAGE == 1) {
                g_A1[g] = a;
                g_C1[g] = cc;
            } else if (STAGE == 2) {
                float A1 = g_A1[g], C1 = g_C1[g];
                g_A2[g] = a * A1;
                g_C2[g] = fmaf(a, C1, cc);
            } else {
                float A1 = g_A1[g], C1 = g_C1[g];
                float A2 = g_A2[g], C2 = g_C2[g];
                float A3 = a * A2, C3 = fmaf(a, C2, cc);
                // D_{3j+ch} = al[j]*x_ch + be[j]
                float al[3] = {1.f - A1, A1 - A2, A2 - A3};
                float be[3] = {-C1, C1 - C2, C2 - C3};
                const float* xp = x + (size_t)b * 3 * HW + gy * WW + gx;
                float x0 = xp[0], x1 = xp[HW], x2 = xp[2 * HW];
#pragma unroll
                for (int o = 0; o < 3; ++o) {
                    float acc = 0.f;
#pragma unroll
                    for (int j = 0; j < 3; ++j) {
                        float w0 = sw[o * 9 + j * 3 + 0];
                        float w1 = sw[o * 9 + j * 3 + 1];
                        float w2 = sw[o * 9 + j * 3 + 2];
                        acc += al[j] * (w0 * x0 + w1 * x1 + w2 * x2)
                             + be[j] * (w0 + w1 + w2);
                    }
                    out[(size_t)(b * 3 + o) * HW + (size_t)gy * WW + gx] = acc;
                }
            }
            if (i + 1 < r1e) {
                r1 += H1[(i + K) * HP + c] - H1[i * HP + c];
                r2 += H2[(i + K) * HP + c] - H2[i * HP + c];
            }
        }
    }
}

// smem bytes per stage
static constexpr int smem_bytes(int R) {
    int T = 64, E1 = T + 2 * R, E2 = T + 4 * R;
    return (2 * E2 * (E2 + 1) + 2 * E2 * (E1 + 1)) * 4;
}

extern "C" void kernel_launch(void* const* d_in, const int* in_sizes, int n_in,
                              void* d_out, int out_size) {
    const float* x  = (const float*)d_in[0];
    const float* wg = (const float*)d_in[1];
    float* out = (float*)d_out;

    constexpr int S1B = smem_bytes(1);   // ~74 KB
    constexpr int S2B = smem_bytes(3);   // ~90 KB
    constexpr int S3B = smem_bytes(7);   // ~127 KB
    cudaFuncSetAttribute(stage_kernel<1, 1>, cudaFuncAttributeMaxDynamicSharedMemorySize, S1B);
    cudaFuncSetAttribute(stage_kernel<3, 2>, cudaFuncAttributeMaxDynamicSharedMemorySize, S2B);
    cudaFuncSetAttribute(stage_kernel<7, 3>, cudaFuncAttributeMaxDynamicSharedMemorySize, S3B);

    dim3 grid(WW / 64, HH / 64, BB);
    stage_kernel<1, 1><<<grid, NT, S1B>>>(x, wg, out);
    stage_kernel<3, 2><<<grid, NT, S2B>>>(x, wg, out);
    stage_kernel<7, 3><<<grid, NT, S3B>>>(x, wg, out);
}

// round 3
// speedup vs baseline: 2.5831x; 1.3500x over previous
#include <cuda_runtime.h>

// Problem shape (fixed by dataset): x_hr (16,3,512,512) f32, w1 (3,9) f32.
#define BB 16
#define HH 512
#define WW 512
#define HW (HH*WW)
#define NPIX (BB*HW)
#define NT 512   // threads per block

// Per-pixel scratch maps (__device__ globals are allowed).
__device__ float2 g_uv[NPIX];   // (sum_c x, sum_c x^2)
__device__ float2 g_P1[NPIX];   // cumulative affine after stage 1: F1 = P.x * x + P.y
__device__ float2 g_P2[NPIX];   // cumulative affine after stage 2
__constant__ float cw[27];      // 1x1 conv weights (3x9)

// One guided-filter stage, fully fused (box -> pointwise -> box -> epilogue).
// All passes segmented to keep ~NT lanes busy; each work item slides BOTH maps
// (dual accumulators) for 2x ILP and half the index math.
template <int R, int STAGE, int T>
__global__ void __launch_bounds__(NT, 2) stage_kernel(const float* __restrict__ x,
                                                      float* __restrict__ out) {
    constexpr int K  = 2 * R + 1;
    constexpr int E1 = T + 2 * R;   // region where A,b are needed
    constexpr int E2 = T + 4 * R;   // region where channel sums are needed
    constexpr int SP = E2 + 1;      // odd strides -> conflict-free
    constexpr int HP = E1 + 1;
    constexpr float EPS = (STAGE == 1) ? 0.16f : ((STAGE == 2) ? 0.04f : 0.01f);

    constexpr int NS1 = NT / E2;                 // segments: H pass 1
    constexpr int LS1 = (E1 + NS1 - 1) / NS1;
    constexpr int NV1 = NT / E1;                 // segments: V pass 1
    constexpr int LV1 = (E1 + NV1 - 1) / NV1;
    constexpr int NS2 = NT / E1;                 // segments: H pass 2
    constexpr int LS2 = (T + NS2 - 1) / NS2;
    constexpr int NV2 = NT / T;                  // segments: V pass 2
    constexpr int LV2 = (T + NV2 - 1) / NV2;

    extern __shared__ float sm[];
    float* S1 = sm;                 // map-1 tile (channel sum, later A, strided SP)
    float* S2 = S1 + E2 * SP;       // map-2 tile (channel sumsq, later b)
    float* H1 = S2 + E2 * SP;       // horizontal scratch (strided HP)
    float* H2 = H1 + E2 * HP;
    float* ry = H2 + E2 * HP;       // E1 row border factors: 1/cy (0 outside image)

    const int tid = threadIdx.x;
    const int gx0 = blockIdx.x * T;
    const int gy0 = blockIdx.y * T;
    const int b   = blockIdx.z;
    const int gb  = b * HW;

    // row border-factor table (doubles as out-of-image mask)
    if (tid < E1) {
        int gy = gy0 - R + tid;
        float r = 0.f;
        if ((unsigned)gy < (unsigned)HH) {
            int cy = min(gy + R, HH - 1) - max(gy - R, 0) + 1;
            r = __frcp_rn((float)cy);
        }
        ry[tid] = r;
    }

    // ---- load channel-sum maps over E2 x E2 (zero padding outside image) ----
    for (int idx = tid; idx < E2 * E2; idx += NT) {
        int iy = idx / E2, ix = idx - iy * E2;
        int gy = gy0 - 2 * R + iy, gx = gx0 - 2 * R + ix;
        float s1 = 0.f, s2 = 0.f;
        if ((unsigned)gy < (unsigned)HH && (unsigned)gx < (unsigned)WW) {
            int g = gb + gy * WW + gx;
            if (STAGE == 1) {
                const float* xb = x + (size_t)b * 3 * HW + gy * WW + gx;
                float x0 = xb[0], x1 = xb[HW], x2 = xb[2 * HW];
                s1 = x0 + x1 + x2;
                s2 = x0 * x0 + x1 * x1 + x2 * x2;
                if (iy >= 2 * R && iy < 2 * R + T && ix >= 2 * R && ix < 2 * R + T)
                    g_uv[g] = make_float2(s1, s2);   // persist for later stages
            } else {
                float2 uv = g_uv[g];
                float2 P  = (STAGE == 2) ? g_P1[g] : g_P2[g];
                // F_c = P.x*x_c + P.y : sum F = P.x*u + 3P.y ; sum F^2 = P.x^2 v + 2 P.x P.y u + 3 P.y^2
                s1 = fmaf(P.x, uv.x, 3.f * P.y);
                s2 = fmaf(P.x * P.x, uv.y, fmaf(2.f * P.x * P.y, uv.x, 3.f * P.y * P.y));
            }
        }
        S1[iy * SP + ix] = s1;
        S2[iy * SP + ix] = s2;
    }
    __syncthreads();

    // ---- box #1 horizontal: H[r][c] = sum_{j=c..c+2R} S[r][j], r<E2, c<E1 ----
    for (int item = tid; item < E2 * NS1; item += NT) {
        int r = item % E2, seg = item / E2;
        int c0 = seg * LS1, c1 = min(E1, c0 + LS1);
        if (c0 >= c1) continue;
        const float* p1 = S1 + r * SP;
        const float* p2 = S2 + r * SP;
        float* o1 = H1 + r * HP;
        float* o2 = H2 + r * HP;
        float a = 0.f, bb = 0.f;
#pragma unroll
        for (int j = 0; j < K; ++j) { a += p1[c0 + j]; bb += p2[c0 + j]; }
        o1[c0] = a; o2[c0] = bb;
        for (int c = c0 + 1; c < c1; ++c) {
            a  += p1[c + 2 * R] - p1[c - 1];
            bb += p2[c + 2 * R] - p2[c - 1];
            o1[c] = a; o2[c] = bb;
        }
    }
    __syncthreads();

    // ---- box #1 vertical + pointwise -> A,b over E1 x E1 (into S1,S2) ----
    for (int item = tid; item < E1 * NV1; item += NT) {
        int c = item % E1, seg = item / E1;
        int r0 = seg * LV1, re = min(E1, r0 + LV1);
        if (r0 >= re) continue;
        int gx = gx0 - R + c;
        float rx = 0.f;
        if ((unsigned)gx < (unsigned)WW) {
            int cx = min(gx + R, WW - 1) - max(gx - R, 0) + 1;
            rx = __frcp_rn(3.f * (float)cx);
        }
        float a1 = 0.f, a2 = 0.f;
#pragma unroll
        for (int j = 0; j < K; ++j) { a1 += H1[(r0 + j) * HP + c]; a2 += H2[(r0 + j) * HP + c]; }
        for (int i = r0;;) {
            float inv = ry[i] * rx;          // 1/Nc, 0 outside image -> A=b=0
            float m = a1 * inv, q = a2 * inv;
            float var = fmaf(-m, m, q);
            float rr = __frcp_rn(var + EPS); // single MUFU per pixel
            float A  = var * rr;
            float bv = m * (EPS * rr);       // b = m*(1-A)
            S1[i * SP + c] = A;
            S2[i * SP + c] = bv;
            if (++i >= re) break;
            a1 += H1[(i - 1 + K) * HP + c] - H1[(i - 1) * HP + c];
            a2 += H2[(i - 1 + K) * HP + c] - H2[(i - 1) * HP + c];
        }
    }
    __syncthreads();

    // ---- box #2 horizontal: H[r][c] = sum_{j=c..c+2R} Ab[r][j], r<E1, c<T ----
    for (int item = tid; item < E1 * NS2; item += NT) {
        int r = item % E1, seg = item / E1;
        int c0 = seg * LS2, c1 = min(T, c0 + LS2);
        if (c0 >= c1) continue;
        const float* p1 = S1 + r * SP;
        const float* p2 = S2 + r * SP;
        float* o1 = H1 + r * HP;
        float* o2 = H2 + r * HP;
        float a = 0.f, bb = 0.f;
#pragma unroll
        for (int j = 0; j < K; ++j) { a += p1[c0 + j]; bb += p2[c0 + j]; }
        o1[c0] = a; o2[c0] = bb;
        for (int c = c0 + 1; c < c1; ++c) {
            a  += p1[c + 2 * R] - p1[c - 1];
            bb += p2[c + 2 * R] - p2[c - 1];
            o1[c] = a; o2[c] = bb;
        }
    }
    __syncthreads();

    // ---- box #2 vertical + fused epilogue over T x T ----
    for (int item = tid; item < T * NV2; item += NT) {
        int c = item % T, seg = item / T;
        int r0 = seg * LV2, re = min(T, r0 + LV2);
        if (r0 >= re) continue;
        int gx = gx0 + c;
        float a1 = 0.f, a2 = 0.f;
#pragma unroll
        for (int j = 0; j < K; ++j) { a1 += H1[(r0 + j) * HP + c]; a2 += H2[(r0 + j) * HP + c]; }
        for (int i = r0;;) {
            int gy = gy0 + i;
            if (gy < HH && gx < WW) {        // partial-tile guard (stage 3, T=48)
                int g = gb + gy * WW + gx;
                float a  = 3.f * a1;         // mean_A = C * box(A), C = 3
                float cc = 3.f * a2;         // mean_b
                if (STAGE == 1) {
                    g_P1[g] = make_float2(a, cc);
                } else if (STAGE == 2) {
                    float2 p = g_P1[g];
                    g_P2[g] = make_float2(a * p.x, fmaf(a, p.y, cc));
                } else {
                    float2 p1 = g_P1[g], p2 = g_P2[g];
                    float A3 = a * p2.x, C3 = fmaf(a, p2.y, cc);
                    float al0 = 1.f - p1.x, be0 = -p1.y;
                    float al1 = p1.x - p2.x, be1 = p1.y - p2.y;
                    float al2 = p2.x - A3,   be2 = p2.y - C3;
                    const float* xp = x + (size_t)b * 3 * HW + gy * WW + gx;
                    float x0 = xp[0], x1 = xp[HW], x2 = xp[2 * HW];
                    float d0 = fmaf(al0, x0, be0), d1 = fmaf(al0, x1, be0), d2 = fmaf(al0, x2, be0);
                    float d3 = fmaf(al1, x0, be1), d4 = fmaf(al1, x1, be1), d5 = fmaf(al1, x2, be1);
                    float d6 = fmaf(al2, x0, be2), d7 = fmaf(al2, x1, be2), d8 = fmaf(al2, x2, be2);
#pragma unroll
                    for (int o = 0; o < 3; ++o) {
                        float acc =      cw[o * 9 + 0] * d0;
                        acc = fmaf(cw[o * 9 + 1], d1, acc);
                        acc = fmaf(cw[o * 9 + 2], d2, acc);
                        acc = fmaf(cw[o * 9 + 3], d3, acc);
                        acc = fmaf(cw[o * 9 + 4], d4, acc);
                        acc = fmaf(cw[o * 9 + 5], d5, acc);
                        acc = fmaf(cw[o * 9 + 6], d6, acc);
                        acc = fmaf(cw[o * 9 + 7], d7, acc);
                        acc = fmaf(cw[o * 9 + 8], d8, acc);
                        out[(size_t)(b * 3 + o) * HW + (size_t)gy * WW + gx] = acc;
                    }
                }
            }
            if (++i >= re) break;
            a1 += H1[(i - 1 + K) * HP + c] - H1[(i - 1) * HP + c];
            a2 += H2[(i - 1 + K) * HP + c] - H2[(i - 1) * HP + c];
        }
    }
}

static constexpr int smem_bytes(int R, int T) {
    int E1 = T + 2 * R, E2 = T + 4 * R;
    return (2 * E2 * (E2 + 1) + 2 * E2 * (E1 + 1) + E1) * 4;
}

extern "C" void kernel_launch(void* const* d_in, const int* in_sizes, int n_in,
                              void* d_out, int out_size) {
    const float* x  = (const float*)d_in[0];
    const float* wg = (const float*)d_in[1];
    float* out = (float*)d_out;

    // weights -> constant memory (device-to-device copy; graph-capturable)
    cudaMemcpyToSymbolAsync(cw, wg, 27 * sizeof(float), 0, cudaMemcpyDeviceToDevice);

    constexpr int S1B = smem_bytes(1, 64);   // ~74 KB -> 2-3 blocks/SM
    constexpr int S2B = smem_bytes(3, 64);   // ~90 KB -> 2 blocks/SM
    constexpr int S3B = smem_bytes(7, 48);   // ~85 KB -> 2 blocks/SM
    cudaFuncSetAttribute((const void*)stage_kernel<1, 1, 64>, cudaFuncAttributeMaxDynamicSharedMemorySize, S1B);
    cudaFuncSetAttribute((const void*)stage_kernel<3, 2, 64>, cudaFuncAttributeMaxDynamicSharedMemorySize, S2B);
    cudaFuncSetAttribute((const void*)stage_kernel<7, 3, 48>, cudaFuncAttributeMaxDynamicSharedMemorySize, S3B);

    dim3 g12(WW / 64, HH / 64, BB);
    stage_kernel<1, 1, 64><<<g12, NT, S1B>>>(x, out);
    stage_kernel<3, 2, 64><<<g12, NT, S2B>>>(x, out);
    dim3 g3((WW + 47) / 48, (HH + 47) / 48, BB);
    stage_kernel<7, 3, 48><<<g3, NT, S3B>>>(x, out);
}

// round 4
// speedup vs baseline: 2.6422x; 1.0229x over previous
#include <cuda_runtime.h>

// Problem shape (fixed by dataset): x_hr (16,3,512,512) f32, w1 (3,9) f32.
#define BB 16
#define HH 512
#define WW 512
#define HW (HH*WW)
#define NPIX (BB*HW)
#define NT 512   // threads per block

// Per-pixel scratch maps (__device__ globals are allowed).
__device__ float2 g_uv[NPIX];   // (sum_c x, sum_c x^2)
__device__ float2 g_P1[NPIX];   // cumulative affine after stage 1: F1 = P.x * x + P.y
__device__ float2 g_P2[NPIX];   // cumulative affine after stage 2
__constant__ float cw[27];      // 1x1 conv weights (3x9)

// One guided-filter stage, fully fused (box -> pointwise -> box -> epilogue).
// Both per-pixel maps live interleaved in float2 shared arrays: every smem
// access is a single 64-bit LDS/STS (half the instructions of scalar pairs).
template <int R, int STAGE, int T>
__global__ void __launch_bounds__(NT, 2) stage_kernel(const float* __restrict__ x,
                                                      float* __restrict__ out) {
    constexpr int K  = 2 * R + 1;
    constexpr int E1 = T + 2 * R;   // region where A,b are needed
    constexpr int E2 = T + 4 * R;   // region where channel sums are needed
    constexpr int SP = E2 + 1;      // odd float2 stride -> conflict-free row access
    constexpr int HP = E1 + 1;
    constexpr float EPS = (STAGE == 1) ? 0.16f : ((STAGE == 2) ? 0.04f : 0.01f);

    constexpr int NS1 = NT / E2;                 // segments: H pass 1
    constexpr int LS1 = (E1 + NS1 - 1) / NS1;
    constexpr int NV1 = NT / E1;                 // segments: V pass 1
    constexpr int LV1 = (E1 + NV1 - 1) / NV1;
    constexpr int NS2 = NT / E1;                 // segments: H pass 2
    constexpr int LS2 = (T + NS2 - 1) / NS2;
    constexpr int NV2 = NT / T;                  // segments: V pass 2
    constexpr int LV2 = (T + NV2 - 1) / NV2;

    extern __shared__ float2 sm2[];
    float2* SS = sm2;                 // E2 x SP tile: (s1,s2), later (A,b)
    float2* Hs = SS + E2 * SP;        // E2 x HP horizontal-box scratch
    float*  ry = (float*)(Hs + E2 * HP);  // E1 row border factors (0 outside image)

    const int tid = threadIdx.x;
    const int gx0 = blockIdx.x * T;
    const int gy0 = blockIdx.y * T;
    const int b   = blockIdx.z;
    const int gb  = b * HW;

    // row border-factor table (doubles as out-of-image mask)
    if (tid < E1) {
        int gy = gy0 - R + tid;
        float r = 0.f;
        if ((unsigned)gy < (unsigned)HH) {
            int cy = min(gy + R, HH - 1) - max(gy - R, 0) + 1;
            r = __frcp_rn((float)cy);
        }
        ry[tid] = r;
    }

    // ---- load channel-sum maps over E2 x E2 (zero padding outside image) ----
    for (int idx = tid; idx < E2 * E2; idx += NT) {
        int iy = idx / E2, ix = idx - iy * E2;
        int gy = gy0 - 2 * R + iy, gx = gx0 - 2 * R + ix;
        float2 s = make_float2(0.f, 0.f);
        if ((unsigned)gy < (unsigned)HH && (unsigned)gx < (unsigned)WW) {
            int g = gb + gy * WW + gx;
            if (STAGE == 1) {
                const float* xb = x + (size_t)b * 3 * HW + gy * WW + gx;
                float x0 = xb[0], x1 = xb[HW], x2 = xb[2 * HW];
                s.x = x0 + x1 + x2;
                s.y = x0 * x0 + x1 * x1 + x2 * x2;
                if (iy >= 2 * R && iy < 2 * R + T && ix >= 2 * R && ix < 2 * R + T)
                    g_uv[g] = s;   // persist for later stages
            } else {
                float2 uv = g_uv[g];
                float2 P  = (STAGE == 2) ? g_P1[g] : g_P2[g];
                // F_c = P.x*x_c + P.y : sumF = P.x*u + 3P.y ; sumF^2 = P.x^2 v + 2PxPy u + 3Py^2
                s.x = fmaf(P.x, uv.x, 3.f * P.y);
                s.y = fmaf(P.x * P.x, uv.y, fmaf(2.f * P.x * P.y, uv.x, 3.f * P.y * P.y));
            }
        }
        SS[iy * SP + ix] = s;
    }
    __syncthreads();

    // ---- box #1 horizontal: Hs[r][c] = sum_{j=c..c+2R} SS[r][j], r<E2, c<E1 ----
    for (int item = tid; item < E2 * NS1; item += NT) {
        int r = item % E2, seg = item / E2;
        int c0 = seg * LS1, c1 = min(E1, c0 + LS1);
        if (c0 >= c1) continue;
        const float2* p = SS + r * SP;
        float2* o = Hs + r * HP;
        float ax = 0.f, ay = 0.f;
#pragma unroll
        for (int j = 0; j < K; ++j) { float2 v = p[c0 + j]; ax += v.x; ay += v.y; }
        o[c0] = make_float2(ax, ay);
        for (int c = c0 + 1; c < c1; ++c) {
            float2 vin = p[c + 2 * R], vout = p[c - 1];
            ax += vin.x - vout.x;
            ay += vin.y - vout.y;
            o[c] = make_float2(ax, ay);
        }
    }
    __syncthreads();

    // ---- box #1 vertical + pointwise -> (A,b) over E1 x E1 (into SS) ----
    for (int item = tid; item < E1 * NV1; item += NT) {
        int c = item % E1, seg = item / E1;
        int r0 = seg * LV1, re = min(E1, r0 + LV1);
        if (r0 >= re) continue;
        int gx = gx0 - R + c;
        float rx = 0.f;
        if ((unsigned)gx < (unsigned)WW) {
            int cx = min(gx + R, WW - 1) - max(gx - R, 0) + 1;
            rx = __frcp_rn(3.f * (float)cx);
        }
        float a1 = 0.f, a2 = 0.f;
#pragma unroll
        for (int j = 0; j < K; ++j) { float2 v = Hs[(r0 + j) * HP + c]; a1 += v.x; a2 += v.y; }
        for (int i = r0;;) {
            float inv = ry[i] * rx;          // 1/Nc, 0 outside image -> A=b=0
            float m = a1 * inv, q = a2 * inv;
            float var = fmaf(-m, m, q);
            float rr = __frcp_rn(var + EPS); // single MUFU per pixel
            float A  = var * rr;
            float bv = m * (EPS * rr);       // b = m*(1-A)
            SS[i * SP + c] = make_float2(A, bv);
            if (++i >= re) break;
            float2 vin = Hs[(i - 1 + K) * HP + c], vout = Hs[(i - 1) * HP + c];
            a1 += vin.x - vout.x;
            a2 += vin.y - vout.y;
        }
    }
    __syncthreads();

    // ---- box #2 horizontal: Hs[r][c] = sum_{j=c..c+2R} SS[r][j], r<E1, c<T ----
    for (int item = tid; item < E1 * NS2; item += NT) {
        int r = item % E1, seg = item / E1;
        int c0 = seg * LS2, c1 = min(T, c0 + LS2);
        if (c0 >= c1) continue;
        const float2* p = SS + r * SP;
        float2* o = Hs + r * HP;
        float ax = 0.f, ay = 0.f;
#pragma unroll
        for (int j = 0; j < K; ++j) { float2 v = p[c0 + j]; ax += v.x; ay += v.y; }
        o[c0] = make_float2(ax, ay);
        for (int c = c0 + 1; c < c1; ++c) {
            float2 vin = p[c + 2 * R], vout = p[c - 1];
            ax += vin.x - vout.x;
            ay += vin.y - vout.y;
            o[c] = make_float2(ax, ay);
        }
    }
    __syncthreads();

    // ---- box #2 vertical + fused epilogue over T x T ----
    for (int item = tid; item < T * NV2; item += NT) {
        int c = item % T, seg = item / T;
        int r0 = seg * LV2, re = min(T, r0 + LV2);
        if (r0 >= re) continue;
        int gx = gx0 + c;
        float a1 = 0.f, a2 = 0.f;
#pragma unroll
        for (int j = 0; j < K; ++j) { float2 v = Hs[(r0 + j) * HP + c]; a1 += v.x; a2 += v.y; }
        for (int i = r0;;) {
            int gy = gy0 + i;
            if (gy < HH && gx < WW) {        // partial-tile guard (stage 3)
                int g = gb + gy * WW + gx;
                float a  = 3.f * a1;         // mean_A = C * box(A), C = 3
                float cc = 3.f * a2;         // mean_b
                if (STAGE == 1) {
                    g_P1[g] = make_float2(a, cc);
                } else if (STAGE == 2) {
                    float2 p = g_P1[g];
                    g_P2[g] = make_float2(a * p.x, fmaf(a, p.y, cc));
                } else {
                    float2 p1 = g_P1[g], p2 = g_P2[g];
                    float A3 = a * p2.x, C3 = fmaf(a, p2.y, cc);
                    float al0 = 1.f - p1.x, be0 = -p1.y;
                    float al1 = p1.x - p2.x, be1 = p1.y - p2.y;
                    float al2 = p2.x - A3,   be2 = p2.y - C3;
                    const float* xp = x + (size_t)b * 3 * HW + gy * WW + gx;
                    float x0 = xp[0], x1 = xp[HW], x2 = xp[2 * HW];
                    float d0 = fmaf(al0, x0, be0), d1 = fmaf(al0, x1, be0), d2 = fmaf(al0, x2, be0);
                    float d3 = fmaf(al1, x0, be1), d4 = fmaf(al1, x1, be1), d5 = fmaf(al1, x2, be1);
                    float d6 = fmaf(al2, x0, be2), d7 = fmaf(al2, x1, be2), d8 = fmaf(al2, x2, be2);
#pragma unroll
                    for (int o = 0; o < 3; ++o) {
                        float acc =      cw[o * 9 + 0] * d0;
                        acc = fmaf(cw[o * 9 + 1], d1, acc);
                        acc = fmaf(cw[o * 9 + 2], d2, acc);
                        acc = fmaf(cw[o * 9 + 3], d3, acc);
                        acc = fmaf(cw[o * 9 + 4], d4, acc);
                        acc = fmaf(cw[o * 9 + 5], d5, acc);
                        acc = fmaf(cw[o * 9 + 6], d6, acc);
                        acc = fmaf(cw[o * 9 + 7], d7, acc);
                        acc = fmaf(cw[o * 9 + 8], d8, acc);
                        out[(size_t)(b * 3 + o) * HW + (size_t)gy * WW + gx] = acc;
                    }
                }
            }
            if (++i >= re) break;
            float2 vin = Hs[(i - 1 + K) * HP + c], vout = Hs[(i - 1) * HP + c];
            a1 += vin.x - vout.x;
            a2 += vin.y - vout.y;
        }
    }
}

static constexpr int smem_bytes(int R, int T) {
    int E1 = T + 2 * R, E2 = T + 4 * R;
    return (E2 * (E2 + 1) + E2 * (E1 + 1)) * 8 + E1 * 4;
}

extern "C" void kernel_launch(void* const* d_in, const int* in_sizes, int n_in,
                              void* d_out, int out_size) {
    const float* x  = (const float*)d_in[0];
    const float* wg = (const float*)d_in[1];
    float* out = (float*)d_out;

    // weights -> constant memory (device-to-device copy; graph-capturable)
    cudaMemcpyToSymbolAsync(cw, wg, 27 * sizeof(float), 0, cudaMemcpyDeviceToDevice);

    constexpr int S1B = smem_bytes(1, 64);   // ~74 KB
    constexpr int S2B = smem_bytes(3, 64);   // ~90 KB
    constexpr int S3B = smem_bytes(7, 48);   // ~85 KB -> 2 blocks/SM
    cudaFuncSetAttribute((const void*)stage_kernel<1, 1, 64>, cudaFuncAttributeMaxDynamicSharedMemorySize, S1B);
    cudaFuncSetAttribute((const void*)stage_kernel<3, 2, 64>, cudaFuncAttributeMaxDynamicSharedMemorySize, S2B);
    cudaFuncSetAttribute((const void*)stage_kernel<7, 3, 48>, cudaFuncAttributeMaxDynamicSharedMemorySize, S3B);

    dim3 g12(WW / 64, HH / 64, BB);
    stage_kernel<1, 1, 64><<<g12, NT, S1B>>>(x, out);
    stage_kernel<3, 2, 64><<<g12, NT, S2B>>>(x, out);
    dim3 g3((WW + 47) / 48, (HH + 47) / 48, BB);
    stage_kernel<7, 3, 48><<<g3, NT, S3B>>>(x, out);
}